// round 9
// baseline (speedup 1.0000x reference)
#include <cuda_runtime.h>
#include <cuda_bf16.h>
#include <cstdint>

// BG_LSTM via warp-level HMMA, dual-tile software pipelining.
// 8 clusters x 16 CTAs; each cluster owns 64 batches as two independent
// 32-batch tiles (A, B). CTA rank owns 16 units (64 gate rows). Per step,
// each tile: mbarrier-cluster wait -> stage B planes from L2 -> MMA
// (3-term bf16 split, fp32 accum) -> activations -> packed h store ->
// mbarrier arrives to all peers. Tile B's compute hides tile A's exchange
// latency and vice versa. W_hh SMEM-resident as bf16 hi/lo planes.

#define TT 512
#define RANKS 16
#define NT 128
#define UPC 16
#define MROWS 64
#define ASTR 264

// Packed h: (hi_bf16 << 16) | lo_bf16, [buf][tile(0..15)][batch][unit]
__device__ uint32_t g_hbuf[2][16][32][256];

extern __shared__ __align__(16) char smem_raw[];

// ---- SMEM offsets (from 1KB-aligned base) ----
#define PLANE_A 33792u              // 64*264*2
#define PLANE_B 16896u              // 32*264*2
#define OFF_ALO 33792u
#define OFF_B0  67584u              // tile t: Bhi at OFF_B0 + t*33792
#define OFF_GS  135168u             // tile t: + t*10240 (4 warps x 2560)
#define OFF_XS  155648u             // tile t: + t*2048
#define OFF_MB  159744u             // mbar tile t: + t*8
#define SM_BYTES 160784

// ---------------- asm helpers ----------------
static __device__ __forceinline__ uint32_t smem_u32(const void* p) {
    uint32_t a;
    asm("{ .reg .u64 t; cvta.to.shared.u64 t, %1; cvt.u32.u64 %0, t; }"
        : "=r"(a) : "l"(p));
    return a;
}
static __device__ __forceinline__ uint32_t prmt(uint32_t a, uint32_t b, uint32_t s) {
    uint32_t r; asm("prmt.b32 %0,%1,%2,%3;" : "=r"(r) : "r"(a), "r"(b), "r"(s));
    return r;
}
static __device__ __forceinline__ void sts64(uint32_t a, uint32_t x, uint32_t y) {
    asm volatile("st.shared.v2.u32 [%0], {%1,%2};" :: "r"(a), "r"(x), "r"(y));
}
static __device__ __forceinline__ void sts32f(uint32_t a, float v) {
    asm volatile("st.shared.f32 [%0], %1;" :: "r"(a), "f"(v));
}
static __device__ __forceinline__ void sts32u(uint32_t a, uint32_t v) {
    asm volatile("st.shared.b32 [%0], %1;" :: "r"(a), "r"(v));
}
static __device__ __forceinline__ float lds32f(uint32_t a) {
    float v; asm volatile("ld.shared.f32 %0, [%1];" : "=f"(v) : "r"(a));
    return v;
}
static __device__ __forceinline__ float4 lds128f(uint32_t a) {
    float4 v;
    asm volatile("ld.shared.v4.f32 {%0,%1,%2,%3}, [%4];"
                 : "=f"(v.x), "=f"(v.y), "=f"(v.z), "=f"(v.w) : "r"(a));
    return v;
}
static __device__ __forceinline__ void ldsm4(uint32_t* r, uint32_t a) {
    asm volatile("ldmatrix.sync.aligned.m8n8.x4.shared.b16 {%0,%1,%2,%3}, [%4];"
                 : "=r"(r[0]), "=r"(r[1]), "=r"(r[2]), "=r"(r[3]) : "r"(a));
}
static __device__ __forceinline__ void mma16816(float* c, const uint32_t* a,
                                                const uint32_t* b) {
    asm volatile(
        "mma.sync.aligned.m16n8k16.row.col.f32.bf16.bf16.f32 "
        "{%0,%1,%2,%3},{%4,%5,%6,%7},{%8,%9},{%0,%1,%2,%3};"
        : "+f"(c[0]), "+f"(c[1]), "+f"(c[2]), "+f"(c[3])
        : "r"(a[0]), "r"(a[1]), "r"(a[2]), "r"(a[3]), "r"(b[0]), "r"(b[1]));
}
static __device__ __forceinline__ void mbar_init(uint32_t a, uint32_t cnt) {
    asm volatile("mbarrier.init.shared.b64 [%0], %1;" :: "r"(a), "r"(cnt) : "memory");
}
static __device__ __forceinline__ void mbar_wait(uint32_t a, uint32_t parity) {
    asm volatile(
        "{\n\t.reg .pred P;\n\t"
        "WL_%=:\n\t"
        "mbarrier.try_wait.parity.acquire.cta.shared::cta.b64 P, [%0], %1, 0x989680;\n\t"
        "@P bra.uni WD_%=;\n\t"
        "bra.uni WL_%=;\n\t"
        "WD_%=:\n\t}"
        :: "r"(a), "r"(parity) : "memory");
}
static __device__ __forceinline__ uint32_t mapa_sh(uint32_t a, uint32_t r) {
    uint32_t d; asm("mapa.shared::cluster.u32 %0, %1, %2;" : "=r"(d) : "r"(a), "r"(r));
    return d;
}
static __device__ __forceinline__ void mbar_arrive_remote(uint32_t a) {
    asm volatile("mbarrier.arrive.shared::cluster.b64 _, [%0];" :: "r"(a) : "memory");
}
static __device__ __forceinline__ void fence_cluster() {
    asm volatile("fence.acq_rel.cluster;" ::: "memory");
}
static __device__ __forceinline__ void cluster_arrive_rel() {
    asm volatile("barrier.cluster.arrive.release.aligned;" ::: "memory");
}
static __device__ __forceinline__ void cluster_wait_acq() {
    asm volatile("barrier.cluster.wait.acquire.aligned;" ::: "memory");
}
static __device__ __forceinline__ float tanh_a(float x) {
    float y; asm("tanh.approx.f32 %0, %1;" : "=f"(y) : "f"(x)); return y;
}
static __device__ __forceinline__ float sigm(float x) {
    return fmaf(0.5f, tanh_a(0.5f * x), 0.5f);
}
static __device__ __forceinline__ uint32_t pack_hilo(float v) {
    __nv_bfloat16 h = __float2bfloat16(v);
    __nv_bfloat16 l = __float2bfloat16(v - __bfloat162float(h));
    return ((uint32_t)__bfloat16_as_ushort(h) << 16) |
           (uint32_t)__bfloat16_as_ushort(l);
}

// One full recurrence step for one 32-batch tile.
static __device__ __forceinline__ void tile_step(
    int step, int tl, int batch0t, float* cc,
    uint32_t sAhi, uint32_t sAlo, uint32_t sBhi, uint32_t sBlo,
    uint32_t sGS, uint32_t sXS, uint32_t mbar,
    const float* __restrict__ x, const float* wihr, const float* biasr,
    int t, int lane, int w, int u, int bq, int unit0,
    uint32_t aOff, const uint32_t* bOff)
{
    const int p = step & 1;

    // ---- wait for all peers' h(step) stores ----
    mbar_wait(mbar, (uint32_t)(step & 1));
    fence_cluster();

    // ---- stage B planes: unpack packed h -> hhi/hlo [n=b][k=u] ----
    #pragma unroll
    for (int i = 0; i < 16; i++) {
        int id = t + i * NT;
        int b  = id >> 6;
        int uc = id & 63;
        uint4 v = __ldcg((const uint4*)&g_hbuf[p][tl][b][uc * 4]);
        uint32_t hiA = prmt(v.x, v.y, 0x7632u);
        uint32_t hiB = prmt(v.z, v.w, 0x7632u);
        uint32_t loA = prmt(v.x, v.y, 0x5410u);
        uint32_t loB = prmt(v.z, v.w, 0x5410u);
        uint32_t o = (uint32_t)(b * ASTR * 2 + uc * 8);
        sts64(sBhi + o, hiA, hiB);
        sts64(sBlo + o, loA, loB);
    }
    // ---- stage x chunk every 16 steps ----
    if ((step & 15) == 0) {
        int bx = t >> 2, i4 = t & 3;
        float4 v = __ldg((const float4*)&x[(size_t)(batch0t + bx) * TT + step] + i4);
        uint32_t a0 = sXS + (uint32_t)(((i4 * 4 + 0) * 32 + bx) * 4);
        sts32f(a0,        v.x);
        sts32f(a0 + 128u, v.y);
        sts32f(a0 + 256u, v.z);
        sts32f(a0 + 384u, v.w);
    }
    __syncthreads();

    // ---- MMA: 3-term split over 16 k-tiles ----
    float c0[4] = {0,0,0,0}, c1[4] = {0,0,0,0};
    float c2[4] = {0,0,0,0}, c3[4] = {0,0,0,0};
    uint32_t aHi = sAhi + aOff, aLo = sAlo + aOff;
    uint32_t bh0 = sBhi + bOff[0], bh1 = sBhi + bOff[1];
    uint32_t bl0 = sBlo + bOff[0], bl1 = sBlo + bOff[1];
    #pragma unroll 4
    for (int kt = 0; kt < 16; kt++) {
        uint32_t ah[4], al[4], bh[8], bl[8];
        ldsm4(ah, aHi);  ldsm4(al, aLo);
        ldsm4(bh, bh0);  ldsm4(bh + 4, bh1);
        ldsm4(bl, bl0);  ldsm4(bl + 4, bl1);
        aHi += 32; aLo += 32; bh0 += 32; bh1 += 32; bl0 += 32; bl1 += 32;
        mma16816(c0, ah, bh);      mma16816(c1, ah, bh + 2);
        mma16816(c2, ah, bh + 4);  mma16816(c3, ah, bh + 6);
        mma16816(c0, al, bh);      mma16816(c1, al, bh + 2);
        mma16816(c2, al, bh + 4);  mma16816(c3, al, bh + 6);
        mma16816(c0, ah, bl);      mma16816(c1, ah, bl + 2);
        mma16816(c2, ah, bl + 4);  mma16816(c3, ah, bl + 6);
    }

    // ---- D fragments -> warp-private gates scratch ----
    {
        uint32_t gw = sGS + (uint32_t)(w * 2560);
        int mr = lane >> 2;
        int j0 = 2 * (lane & 3);
        float* cs[4] = {c0, c1, c2, c3};
        #pragma unroll
        for (int nt = 0; nt < 4; nt++) {
            int col = nt * 8 + j0;
            sts32f(gw + (uint32_t)((col    ) * 80 + mr * 4),       cs[nt][0]);
            sts32f(gw + (uint32_t)((col + 1) * 80 + mr * 4),       cs[nt][1]);
            sts32f(gw + (uint32_t)((col    ) * 80 + (mr + 8) * 4), cs[nt][2]);
            sts32f(gw + (uint32_t)((col + 1) * 80 + (mr + 8) * 4), cs[nt][3]);
        }
    }
    __syncwarp();

    // ---- activations: 4 cells (u, 4bq+j) ----
    {
        uint32_t gw = sGS + (uint32_t)(w * 2560) + (uint32_t)((lane >> 3) * 16);
        #pragma unroll
        for (int j = 0; j < 4; j++) {
            int b = 4 * bq + j;
            float4 gv = lds128f(gw + (uint32_t)(b * 80));
            float xv  = lds32f(sXS + (uint32_t)(((step & 15) * 32 + b) * 4));
            float gi = gv.x + fmaf(xv, wihr[0], biasr[0]);
            float gf = gv.y + fmaf(xv, wihr[1], biasr[1]);
            float gg = gv.z + fmaf(xv, wihr[2], biasr[2]);
            float go = gv.w + fmaf(xv, wihr[3], biasr[3]);
            float c = sigm(gf) * cc[j] + sigm(gi) * tanh_a(gg);
            cc[j] = c;
            float hv = sigm(go) * tanh_a(c);
            __stcg(&g_hbuf[p ^ 1][tl][b][unit0 + u], pack_hilo(hv));
        }
    }
    __syncthreads();   // all h stores done before signaling peers

    if (t < RANKS) {
        fence_cluster();
        mbar_arrive_remote(mapa_sh(mbar, (uint32_t)t));
    }
}

__global__ void __launch_bounds__(NT, 1)
lstm_kernel(const float* __restrict__ x,    const float* __restrict__ wih,
            const float* __restrict__ whh,  const float* __restrict__ bih,
            const float* __restrict__ bhh,  const float* __restrict__ wfc,
            const float* __restrict__ bfc,  float* __restrict__ out)
{
    const int t      = threadIdx.x;
    const int lane   = t & 31;
    const int w      = t >> 5;
    const int cta    = blockIdx.x;
    const int rank   = cta % RANKS;
    const int cl     = cta / RANKS;          // 0..7
    const int tlA    = cl * 2, tlB = cl * 2 + 1;
    const int b0A    = cl * 64, b0B = cl * 64 + 32;
    const int unit0  = rank * UPC;

    const uint32_t base = (smem_u32(smem_raw) + 1023u) & ~1023u;
    const uint32_t sAhi  = base;
    const uint32_t sAlo  = base + OFF_ALO;
    const uint32_t sBhiA = base + OFF_B0;
    const uint32_t sBloA = sBhiA + PLANE_B;
    const uint32_t sBhiB = base + OFF_B0 + 33792u;
    const uint32_t sBloB = sBhiB + PLANE_B;
    const uint32_t sGSA  = base + OFF_GS;
    const uint32_t sGSB  = base + OFF_GS + 10240u;
    const uint32_t sXSA  = base + OFF_XS;
    const uint32_t sXSB  = base + OFF_XS + 2048u;
    const uint32_t mbA   = base + OFF_MB;
    const uint32_t mbB   = base + OFF_MB + 8u;

    if (t == 0) { mbar_init(mbA, RANKS); mbar_init(mbB, RANKS); }

    // ---- One-time: W' -> SMEM planes. Row m = u*4+g (u local). ----
    if (t < MROWS) {
        const int m = t;
        const float* wrow = whh + ((size_t)((m & 3) * 256 + unit0 + (m >> 2))) * 256;
        uint32_t ah = sAhi + (uint32_t)(m * ASTR * 2);
        uint32_t al = sAlo + (uint32_t)(m * ASTR * 2);
        #pragma unroll 8
        for (int k2 = 0; k2 < 128; k2++) {
            float2 wv = *(const float2*)(wrow + 2 * k2);
            __nv_bfloat16 hx = __float2bfloat16(wv.x);
            __nv_bfloat16 hy = __float2bfloat16(wv.y);
            float rx = wv.x - __bfloat162float(hx);
            float ry = wv.y - __bfloat162float(hy);
            uint32_t hi = ((uint32_t)__bfloat16_as_ushort(hy) << 16) |
                          (uint32_t)__bfloat16_as_ushort(hx);
            __nv_bfloat16 lx = __float2bfloat16(rx);
            __nv_bfloat16 ly = __float2bfloat16(ry);
            uint32_t lo = ((uint32_t)__bfloat16_as_ushort(ly) << 16) |
                          (uint32_t)__bfloat16_as_ushort(lx);
            sts32u(ah + 4u * k2, hi);
            sts32u(al + 4u * k2, lo);
        }
    }

    // ---- Per-thread activation params (shared by both tiles) ----
    const int u  = t >> 3;
    const int bq = t & 7;
    float wihr[4], biasr[4];
    #pragma unroll
    for (int g = 0; g < 4; g++) {
        int r = g * 256 + unit0 + u;
        wihr[g]  = __ldg(&wih[r]);
        biasr[g] = __ldg(&bih[r]) + __ldg(&bhh[r]);
    }

    // ---- Zero h buffer 0 for both tiles ----
    #pragma unroll
    for (int i = 0; i < 4; i++) {
        __stcg(&g_hbuf[0][tlA][0][0] + rank * 512 + i * NT + t, 0u);
        __stcg(&g_hbuf[0][tlB][0][0] + rank * 512 + i * NT + t, 0u);
    }
    float ccA[4] = {0.f, 0.f, 0.f, 0.f};
    float ccB[4] = {0.f, 0.f, 0.f, 0.f};

    // ---- ldmatrix lane base addresses ----
    const uint32_t aOff =
        (uint32_t)(((16 * w + (lane & 15)) * ASTR + ((lane >> 4) * 8)) * 2);
    uint32_t bOff[2];
    #pragma unroll
    for (int P = 0; P < 2; P++) {
        int nB = 16 * P + (lane & 7) + (((lane >> 4) & 1) << 3);
        int ka = (lane & 8) ? 8 : 0;
        bOff[P] = (uint32_t)((nB * ASTR + ka) * 2);
    }

    __syncthreads();
    cluster_arrive_rel();   // h(0) + mbar init visible cluster-wide
    cluster_wait_acq();

    // ---- prime both mbarriers (completes phase 0) ----
    if (t < RANKS) {
        mbar_arrive_remote(mapa_sh(mbA, (uint32_t)t));
        mbar_arrive_remote(mapa_sh(mbB, (uint32_t)t));
    }

    for (int step = 0; step < TT; step++) {
        tile_step(step, tlA, b0A, ccA, sAhi, sAlo, sBhiA, sBloA, sGSA, sXSA,
                  mbA, x, wihr, biasr, t, lane, w, u, bq, unit0, aOff, bOff);
        tile_step(step, tlB, b0B, ccB, sAhi, sAlo, sBhiB, sBloB, sGSB, sXSB,
                  mbB, x, wihr, biasr, t, lane, w, u, bq, unit0, aOff, bOff);
    }

    // ---- final: wait phase TT (parity 0), then FC head on rank 0 ----
    mbar_wait(mbA, 0u);
    mbar_wait(mbB, 0u);
    fence_cluster();

    if (rank == 0) {
        #pragma unroll 1
        for (int tile = 0; tile < 2; tile++) {
            int tl = cl * 2 + tile;
            int bb0 = cl * 64 + tile * 32;
            uint32_t gs = (tile == 0) ? sGSA : sGSB;
            int b = t >> 2, seg = t & 3;       // 4 segments x 64 units
            float s = 0.f;
            #pragma unroll 8
            for (int j = 0; j < 64; j++) {
                int uu = seg * 64 + j;
                uint32_t pk = __ldcg(&g_hbuf[0][tl][b][uu]);
                float h = __bfloat162float(__ushort_as_bfloat16((unsigned short)(pk >> 16))) +
                          __bfloat162float(__ushort_as_bfloat16((unsigned short)(pk & 0xFFFF)));
                s = fmaf(fmaxf(h, 0.f), __ldg(&wfc[uu]), s);
            }
            sts32f(gs + (uint32_t)((b * 4 + seg) * 4), s);
            __syncthreads();
            if (t < 32) {
                float tot = __ldg(bfc);
                #pragma unroll
                for (int sg = 0; sg < 4; sg++)
                    tot += lds32f(gs + (uint32_t)((t * 4 + sg) * 4));
                out[bb0 + t] = tot;
            }
            __syncthreads();
        }
    }
}

extern "C" void kernel_launch(void* const* d_in, const int* in_sizes, int n_in,
                              void* d_out, int out_size) {
    const float* x   = (const float*)d_in[0];
    const float* wih = (const float*)d_in[1];
    const float* whh = (const float*)d_in[2];
    const float* bih = (const float*)d_in[3];
    const float* bhh = (const float*)d_in[4];
    const float* wfc = (const float*)d_in[5];
    const float* bfc = (const float*)d_in[6];
    (void)in_sizes; (void)n_in; (void)out_size;

    cudaFuncSetAttribute(lstm_kernel,
                         cudaFuncAttributeMaxDynamicSharedMemorySize, SM_BYTES);
    cudaFuncSetAttribute(lstm_kernel,
                         cudaFuncAttributeNonPortableClusterSizeAllowed, 1);

    cudaLaunchConfig_t cfg = {};
    cfg.gridDim  = {128, 1, 1};
    cfg.blockDim = {NT, 1, 1};
    cfg.dynamicSmemBytes = SM_BYTES;
    cudaLaunchAttribute at[1];
    at[0].id = cudaLaunchAttributeClusterDimension;
    at[0].val.clusterDim = {RANKS, 1, 1};
    cfg.attrs = at; cfg.numAttrs = 1;
    cudaLaunchKernelEx(&cfg, lstm_kernel, x, wih, whh, bih, bhh, wfc, bfc,
                       (float*)d_out);
}

// round 10
// speedup vs baseline: 1.4005x; 1.4005x over previous
#include <cuda_runtime.h>
#include <cuda_bf16.h>
#include <cstdint>

// BG_LSTM via warp-level HMMA: B=512, T=512, H=256, in=1.
// 16 clusters x 16 CTAs (non-portable cluster), 256 threads/CTA,
// 2 CTAs/SM. Cluster owns 32 batches; CTA rank owns 16 units (64 gate
// rows). W_hh SMEM-resident as bf16 hi/lo planes. h exchanged through L2
// as SEPARATE hi/lo bf16 planes (no repacking): staging is pure
// LDG.128->STS.128. Warps split N (wm=w&3 -> m-rows, wp=w>>2 -> batches).
// Gates = Whi*hhi + Wlo*hhi + Whi*hlo, fp32 accum. One release/acquire
// cluster barrier per step.

#define TT 512
#define RANKS 16
#define NT 256
#define UPC 16
#define MROWS 64
#define ASTR 264

// h planes: [buf][tile][batch][unit-pair], u32 = (bf16 u+1 <<16)|(bf16 u)
__device__ uint32_t g_hi32[2][16][32][128];
__device__ uint32_t g_lo32[2][16][32][128];

extern __shared__ __align__(16) char smem_raw[];

// ---- SMEM offsets (from 1KB-aligned base) ----
#define OFF_ALO 33792u
#define OFF_BHI 67584u
#define OFF_BLO 84480u
#define OFF_GS  101376u   // 32 x 80 fp32 = 10240
#define OFF_XS  111616u   // 16 steps x 32 b fp32 = 2048
#define SM_BYTES 114688

// ---------------- asm helpers ----------------
static __device__ __forceinline__ uint32_t smem_u32(const void* p) {
    uint32_t a;
    asm("{ .reg .u64 t; cvta.to.shared.u64 t, %1; cvt.u32.u64 %0, t; }"
        : "=r"(a) : "l"(p));
    return a;
}
static __device__ __forceinline__ void sts128(uint32_t a, uint4 v) {
    asm volatile("st.shared.v4.b32 [%0], {%1,%2,%3,%4};"
                 :: "r"(a), "r"(v.x), "r"(v.y), "r"(v.z), "r"(v.w));
}
static __device__ __forceinline__ void sts32f(uint32_t a, float v) {
    asm volatile("st.shared.f32 [%0], %1;" :: "r"(a), "f"(v));
}
static __device__ __forceinline__ void sts32u(uint32_t a, uint32_t v) {
    asm volatile("st.shared.b32 [%0], %1;" :: "r"(a), "r"(v));
}
static __device__ __forceinline__ float lds32f(uint32_t a) {
    float v; asm volatile("ld.shared.f32 %0, [%1];" : "=f"(v) : "r"(a));
    return v;
}
static __device__ __forceinline__ float4 lds128f(uint32_t a) {
    float4 v;
    asm volatile("ld.shared.v4.f32 {%0,%1,%2,%3}, [%4];"
                 : "=f"(v.x), "=f"(v.y), "=f"(v.z), "=f"(v.w) : "r"(a));
    return v;
}
static __device__ __forceinline__ void ldsm4(uint32_t* r, uint32_t a) {
    asm volatile("ldmatrix.sync.aligned.m8n8.x4.shared.b16 {%0,%1,%2,%3}, [%4];"
                 : "=r"(r[0]), "=r"(r[1]), "=r"(r[2]), "=r"(r[3]) : "r"(a));
}
static __device__ __forceinline__ void mma16816(float* c, const uint32_t* a,
                                                const uint32_t* b) {
    asm volatile(
        "mma.sync.aligned.m16n8k16.row.col.f32.bf16.bf16.f32 "
        "{%0,%1,%2,%3},{%4,%5,%6,%7},{%8,%9},{%0,%1,%2,%3};"
        : "+f"(c[0]), "+f"(c[1]), "+f"(c[2]), "+f"(c[3])
        : "r"(a[0]), "r"(a[1]), "r"(a[2]), "r"(a[3]), "r"(b[0]), "r"(b[1]));
}
static __device__ __forceinline__ void cluster_arrive_rel() {
    asm volatile("barrier.cluster.arrive.release.aligned;" ::: "memory");
}
static __device__ __forceinline__ void cluster_wait_acq() {
    asm volatile("barrier.cluster.wait.acquire.aligned;" ::: "memory");
}
static __device__ __forceinline__ float tanh_a(float x) {
    float y; asm("tanh.approx.f32 %0, %1;" : "=f"(y) : "f"(x)); return y;
}
static __device__ __forceinline__ float sigm(float x) {
    return fmaf(0.5f, tanh_a(0.5f * x), 0.5f);
}

__global__ void __launch_bounds__(NT, 1)
lstm_kernel(const float* __restrict__ x,    const float* __restrict__ wih,
            const float* __restrict__ whh,  const float* __restrict__ bih,
            const float* __restrict__ bhh,  const float* __restrict__ wfc,
            const float* __restrict__ bfc,  float* __restrict__ out)
{
    const int t      = threadIdx.x;
    const int lane   = t & 31;
    const int w      = t >> 5;
    const int wm     = w & 3;       // m-row group (16 rows)
    const int wp     = w >> 2;      // batch half (16 batches)
    const int cta    = blockIdx.x;
    const int rank   = cta % RANKS;
    const int cl     = cta / RANKS;     // tile 0..15
    const int batch0 = cl * 32;
    const int unit0  = rank * UPC;

    const uint32_t base = (smem_u32(smem_raw) + 1023u) & ~1023u;
    const uint32_t sAhi = base;
    const uint32_t sAlo = base + OFF_ALO;
    const uint32_t sBhi = base + OFF_BHI;
    const uint32_t sBlo = base + OFF_BLO;
    const uint32_t sGS  = base + OFF_GS;
    const uint32_t sXS  = base + OFF_XS;

    // ---- One-time: W' -> SMEM planes. Row m = u*4+g (u local). ----
    if (t < MROWS) {
        const int m = t;
        const float* wrow = whh + ((size_t)((m & 3) * 256 + unit0 + (m >> 2))) * 256;
        uint32_t ah = sAhi + (uint32_t)(m * ASTR * 2);
        uint32_t al = sAlo + (uint32_t)(m * ASTR * 2);
        #pragma unroll 8
        for (int k2 = 0; k2 < 128; k2++) {
            float2 wv = *(const float2*)(wrow + 2 * k2);
            __nv_bfloat16 hx = __float2bfloat16(wv.x);
            __nv_bfloat16 hy = __float2bfloat16(wv.y);
            float rx = wv.x - __bfloat162float(hx);
            float ry = wv.y - __bfloat162float(hy);
            uint32_t hi = ((uint32_t)__bfloat16_as_ushort(hy) << 16) |
                          (uint32_t)__bfloat16_as_ushort(hx);
            __nv_bfloat16 lx = __float2bfloat16(rx);
            __nv_bfloat16 ly = __float2bfloat16(ry);
            uint32_t lo = ((uint32_t)__bfloat16_as_ushort(ly) << 16) |
                          (uint32_t)__bfloat16_as_ushort(lx);
            sts32u(ah + 4u * k2, hi);
            sts32u(al + 4u * k2, lo);
        }
    }

    // ---- Per-thread activation params: u = t>>4 (0..15), 2 batches ----
    const int u  = t >> 4;
    const int bq = t & 15;
    float wihr[4], biasr[4];
    #pragma unroll
    for (int g = 0; g < 4; g++) {
        int r = g * 256 + unit0 + u;
        wihr[g]  = __ldg(&wih[r]);
        biasr[g] = __ldg(&bih[r]) + __ldg(&bhh[r]);
    }

    // ---- Zero h planes, buffer 0, my tile (1/16 per CTA) ----
    {
        uint32_t* zh = &g_hi32[0][cl][0][0];
        uint32_t* zl = &g_lo32[0][cl][0][0];
        __stcg(&zh[rank * 256 + t], 0u);
        __stcg(&zl[rank * 256 + t], 0u);
    }
    float cc[2] = {0.f, 0.f};

    // ---- ldmatrix lane base addresses ----
    const uint32_t aOff =
        (uint32_t)(((16 * wm + (lane & 15)) * ASTR + ((lane >> 4) * 8)) * 2);
    const int nB = 16 * wp + (lane & 7) + (((lane >> 4) & 1) << 3);
    const uint32_t bOff = (uint32_t)((nB * ASTR + ((lane & 8) ? 8 : 0)) * 2);

    __syncthreads();
    cluster_arrive_rel();
    cluster_wait_acq();

    int p = 0;
    for (int step = 0; step < TT; step++) {
        // ---- Stage B planes: pure LDG.128 -> STS.128 (4+4 per thread) ----
        {
            const uint4* srcH = (const uint4*)&g_hi32[p][cl][0][0];
            const uint4* srcL = (const uint4*)&g_lo32[p][cl][0][0];
            #pragma unroll
            for (int i = 0; i < 4; i++) {
                int id  = t + i * NT;        // 1024 granules of 16B
                int b   = id >> 5;
                int col = id & 31;
                uint32_t o = (uint32_t)(b * (ASTR * 2) + col * 16);
                uint4 vh = __ldcg(&srcH[id]);
                uint4 vl = __ldcg(&srcL[id]);
                sts128(sBhi + o, vh);
                sts128(sBlo + o, vl);
            }
        }
        // ---- Stage x chunk every 16 steps ----
        if ((step & 15) == 0 && t < 128) {
            int bx = t >> 2, i4 = t & 3;
            float4 v = __ldg((const float4*)&x[(size_t)(batch0 + bx) * TT + step] + i4);
            uint32_t a0 = sXS + (uint32_t)(((i4 * 4 + 0) * 32 + bx) * 4);
            sts32f(a0,        v.x);
            sts32f(a0 + 128u, v.y);
            sts32f(a0 + 256u, v.z);
            sts32f(a0 + 384u, v.w);
        }
        __syncthreads();

        // ---- MMA: 3-term split, warp = (wm rows, wp batch half) ----
        float c0[4] = {0,0,0,0}, c1[4] = {0,0,0,0};
        uint32_t aHi = sAhi + aOff, aLo = sAlo + aOff;
        uint32_t bHi = sBhi + bOff, bLo = sBlo + bOff;
        #pragma unroll 4
        for (int kt = 0; kt < 16; kt++) {
            uint32_t ah[4], al[4], bh[4], bl[4];
            ldsm4(ah, aHi);  ldsm4(al, aLo);
            ldsm4(bh, bHi);  ldsm4(bl, bLo);
            aHi += 32; aLo += 32; bHi += 32; bLo += 32;
            mma16816(c0, ah, bh);      mma16816(c1, ah, bh + 2);
            mma16816(c0, al, bh);      mma16816(c1, al, bh + 2);
            mma16816(c0, ah, bl);      mma16816(c1, ah, bl + 2);
        }

        // ---- D fragments -> gates scratch gs[b][m], stride 80 ----
        {
            int m0 = 16 * wm + (lane >> 2);
            int j0 = 2 * (lane & 3);
            #pragma unroll
            for (int nt = 0; nt < 2; nt++) {
                float* cs = nt ? c1 : c0;
                int col = 16 * wp + nt * 8 + j0;
                sts32f(sGS + (uint32_t)(((col    ) * 80 + m0    ) * 4), cs[0]);
                sts32f(sGS + (uint32_t)(((col + 1) * 80 + m0    ) * 4), cs[1]);
                sts32f(sGS + (uint32_t)(((col    ) * 80 + m0 + 8) * 4), cs[2]);
                sts32f(sGS + (uint32_t)(((col + 1) * 80 + m0 + 8) * 4), cs[3]);
            }
        }
        __syncthreads();

        // ---- Activations: 2 cells (u, 2bq+j) ----
        float hv[2];
        #pragma unroll
        for (int j = 0; j < 2; j++) {
            int b = 2 * bq + j;
            float4 gv = lds128f(sGS + (uint32_t)((b * 80 + 4 * u) * 4));
            float xv  = lds32f(sXS + (uint32_t)(((step & 15) * 32 + b) * 4));
            float gi = gv.x + fmaf(xv, wihr[0], biasr[0]);
            float gf = gv.y + fmaf(xv, wihr[1], biasr[1]);
            float gg = gv.z + fmaf(xv, wihr[2], biasr[2]);
            float go = gv.w + fmaf(xv, wihr[3], biasr[3]);
            float c = sigm(gf) * cc[j] + sigm(gi) * tanh_a(gg);
            cc[j] = c;
            hv[j] = sigm(go) * tanh_a(c);
        }
        // ---- Pack unit-pairs via shuffle, store hi/lo planes ----
        {
            float q0 = __shfl_down_sync(0xffffffffu, hv[0], 16);
            float q1 = __shfl_down_sync(0xffffffffu, hv[1], 16);
            if (lane < 16) {
                int up = (unit0 + u) >> 1;   // u even here
                #pragma unroll
                for (int j = 0; j < 2; j++) {
                    int b = 2 * bq + j;
                    float a0 = hv[j], a1 = (j ? q1 : q0);
                    __nv_bfloat16 h0 = __float2bfloat16(a0);
                    __nv_bfloat16 h1 = __float2bfloat16(a1);
                    uint32_t hi = ((uint32_t)__bfloat16_as_ushort(h1) << 16) |
                                  (uint32_t)__bfloat16_as_ushort(h0);
                    __nv_bfloat16 l0 = __float2bfloat16(a0 - __bfloat162float(h0));
                    __nv_bfloat16 l1 = __float2bfloat16(a1 - __bfloat162float(h1));
                    uint32_t lo = ((uint32_t)__bfloat16_as_ushort(l1) << 16) |
                                  (uint32_t)__bfloat16_as_ushort(l0);
                    __stcg(&g_hi32[p ^ 1][cl][b][up], hi);
                    __stcg(&g_lo32[p ^ 1][cl][b][up], lo);
                }
            }
        }

        cluster_arrive_rel();
        cluster_wait_acq();
        p ^= 1;
    }

    // ---- FC head (rank 0 CTA of each cluster); final h in buffer 0 ----
    if (rank == 0) {
        int b = t >> 3, seg = t & 7;   // 8 segments x 16 unit-pairs
        float s = 0.f;
        #pragma unroll 4
        for (int jj = 0; jj < 16; jj++) {
            int q = seg * 16 + jj;     // unit pair -> units 2q, 2q+1
            uint32_t hi = __ldcg(&g_hi32[0][cl][b][q]);
            uint32_t lo = __ldcg(&g_lo32[0][cl][b][q]);
            float h0 = __bfloat162float(__ushort_as_bfloat16((unsigned short)(hi & 0xFFFF))) +
                       __bfloat162float(__ushort_as_bfloat16((unsigned short)(lo & 0xFFFF)));
            float h1 = __bfloat162float(__ushort_as_bfloat16((unsigned short)(hi >> 16))) +
                       __bfloat162float(__ushort_as_bfloat16((unsigned short)(lo >> 16)));
            s = fmaf(fmaxf(h0, 0.f), __ldg(&wfc[2 * q]),     s);
            s = fmaf(fmaxf(h1, 0.f), __ldg(&wfc[2 * q + 1]), s);
        }
        sts32f(sGS + (uint32_t)((b * 8 + seg) * 4), s);
        __syncthreads();
        if (t < 32) {
            float tot = __ldg(bfc);
            #pragma unroll
            for (int sg = 0; sg < 8; sg++)
                tot += lds32f(sGS + (uint32_t)((t * 8 + sg) * 4));
            out[batch0 + t] = tot;
        }
    }
}

extern "C" void kernel_launch(void* const* d_in, const int* in_sizes, int n_in,
                              void* d_out, int out_size) {
    const float* x   = (const float*)d_in[0];
    const float* wih = (const float*)d_in[1];
    const float* whh = (const float*)d_in[2];
    const float* bih = (const float*)d_in[3];
    const float* bhh = (const float*)d_in[4];
    const float* wfc = (const float*)d_in[5];
    const float* bfc = (const float*)d_in[6];
    (void)in_sizes; (void)n_in; (void)out_size;

    cudaFuncSetAttribute(lstm_kernel,
                         cudaFuncAttributeMaxDynamicSharedMemorySize, SM_BYTES);
    cudaFuncSetAttribute(lstm_kernel,
                         cudaFuncAttributeNonPortableClusterSizeAllowed, 1);

    cudaLaunchConfig_t cfg = {};
    cfg.gridDim  = {256, 1, 1};
    cfg.blockDim = {NT, 1, 1};
    cfg.dynamicSmemBytes = SM_BYTES;
    cudaLaunchAttribute at[1];
    at[0].id = cudaLaunchAttributeClusterDimension;
    at[0].val.clusterDim = {RANKS, 1, 1};
    cfg.attrs = at; cfg.numAttrs = 1;
    cudaLaunchKernelEx(&cfg, lstm_kernel, x, wih, whh, bih, bhh, wfc, bfc,
                       (float*)d_out);
}